// round 1
// baseline (speedup 1.0000x reference)
#include <cuda_runtime.h>
#include <math.h>

// Problem dims (fixed by reference)
#define B_   1024
#define H1   500
#define IN_  784
#define NOUT 10
#define T_   100

#define BM 64
#define BN 64
#define BK 16

// Scratch (no allocations allowed)
__device__ float g_h[B_ * H1];
__device__ float g_drive[B_ * H1];
__device__ float g_u[B_ * NOUT];

// C[M,N] = act(A[M,K] @ B[N,K]^T + bias[N])
// ACT: 0 none, 1 relu, 2 sigmoid
template<int M, int N, int K, int ACT>
__device__ __forceinline__ void gemm_body(const float* __restrict__ A,
                                          const float* __restrict__ Bw,
                                          const float* __restrict__ bias,
                                          float* __restrict__ C) {
    __shared__ float As[BK][BM];
    __shared__ float Bs[BK][BN];
    const int tid = threadIdx.x;           // 256 threads
    const int tx = tid & 15, ty = tid >> 4;
    const int m0 = blockIdx.y * BM, n0 = blockIdx.x * BN;
    const int lrow = tid >> 2;             // 0..63
    const int lcol = (tid & 3) * 4;        // 0,4,8,12

    float acc[4][4];
#pragma unroll
    for (int i = 0; i < 4; i++)
#pragma unroll
        for (int j = 0; j < 4; j++) acc[i][j] = 0.0f;

    for (int k0 = 0; k0 < K; k0 += BK) {
        const int gm = m0 + lrow;          // M % BM == 0 for our grids -> always valid
        const int gn = n0 + lrow;
#pragma unroll
        for (int i = 0; i < 4; i++) {
            const int gk = k0 + lcol + i;
            As[lcol + i][lrow] = (gk < K) ? A[gm * K + gk] : 0.0f;
            Bs[lcol + i][lrow] = (gn < N && gk < K) ? Bw[gn * K + gk] : 0.0f;
        }
        __syncthreads();
#pragma unroll
        for (int kk = 0; kk < BK; kk++) {
            float a[4], b[4];
#pragma unroll
            for (int i = 0; i < 4; i++) a[i] = As[kk][ty * 4 + i];
#pragma unroll
            for (int j = 0; j < 4; j++) b[j] = Bs[kk][tx * 4 + j];
#pragma unroll
            for (int i = 0; i < 4; i++)
#pragma unroll
                for (int j = 0; j < 4; j++)
                    acc[i][j] = fmaf(a[i], b[j], acc[i][j]);
        }
        __syncthreads();
    }

#pragma unroll
    for (int i = 0; i < 4; i++) {
        const int m = m0 + ty * 4 + i;
#pragma unroll
        for (int j = 0; j < 4; j++) {
            const int n = n0 + tx * 4 + j;
            if (n < N) {
                float x = acc[i][j] + bias[n];
                if (ACT == 1) x = fmaxf(x, 0.0f);
                if (ACT == 2) {
                    // numerically stable sigmoid (matches jax.nn.sigmoid)
                    if (x >= 0.0f) {
                        x = 1.0f / (1.0f + expf(-x));
                    } else {
                        const float e = expf(x);
                        x = e / (1.0f + e);
                    }
                }
                C[m * N + n] = x;
            }
        }
    }
}

__global__ void k_gemm1(const float* __restrict__ x,
                        const float* __restrict__ w1,
                        const float* __restrict__ b1) {
    gemm_body<B_, H1, IN_, 1>(x, w1, b1, g_h);
}

__global__ void k_gemm2(const float* __restrict__ w2,
                        const float* __restrict__ b2) {
    gemm_body<B_, H1, H1, 2>(g_h, w2, b2, g_drive);
}

// u[m,n] = sum_k drive[m,k] * w3[n,k]   (b3 added in the scan)
__global__ void k_gemm3(const float* __restrict__ w3) {
    const int m = blockIdx.x;
    __shared__ float row[H1];
    __shared__ float part[250];
    const int tid = threadIdx.x;  // 256
    for (int k = tid; k < H1; k += 256) row[k] = g_drive[m * H1 + k];
    __syncthreads();
    if (tid < 250) {
        const int n = tid / 25;
        const int ks = (tid % 25) * 20;
        float s = 0.0f;
#pragma unroll
        for (int k = 0; k < 20; k++)
            s = fmaf(row[ks + k], w3[n * H1 + ks + k], s);
        part[tid] = s;
    }
    __syncthreads();
    if (tid < NOUT) {
        float s = 0.0f;
#pragma unroll
        for (int p = 0; p < 25; p++) s += part[tid * 25 + p];
        g_u[m * NOUT + tid] = s;
    }
}

// LIF scan: v = sigma*v*(1-s) + c[t]*u + b3; s = (v >= 1)
// c[t] scalar recurrence computed in fp64 (exact closed-form of the psp IIR).
__global__ void k_scan(const float* __restrict__ b3, float* __restrict__ out) {
    const int id = blockIdx.x * blockDim.x + threadIdx.x;
    if (id >= B_ * NOUT) return;
    const int j = id % NOUT;
    const float uu = g_u[id];
    const float bb = b3[j];
    const float SIGMA = 0.7788007830714049f;   // exp(-1/4)
    const double A1 = 1.1466802242428472;      // exp(-1/4)+exp(-1)
    const double A2 = -0.2865047968601901;     // -exp(-1/4)*exp(-1)

    double c1 = 0.0, c2 = 0.0;
    float v = 0.0f, s = 0.0f;
    float* o = out + id * T_;
#pragma unroll 4
    for (int t = 0; t < T_; t++) {
        const double c = A1 * c1 + A2 * c2 + 1.0;
        const float cur = __fadd_rn(__fmul_rn((float)c, uu), bb);
        float a = __fmul_rn(SIGMA, v);
        a = __fmul_rn(a, 1.0f - s);
        v = __fadd_rn(a, cur);
        s = (v >= 1.0f) ? 1.0f : 0.0f;
        o[t] = s;
        c2 = c1;
        c1 = c;
    }
}

extern "C" void kernel_launch(void* const* d_in, const int* in_sizes, int n_in,
                              void* d_out, int out_size) {
    const float* x  = (const float*)d_in[0];
    const float* w1 = (const float*)d_in[1];
    const float* b1 = (const float*)d_in[2];
    const float* w2 = (const float*)d_in[3];
    const float* b2 = (const float*)d_in[4];
    const float* w3 = (const float*)d_in[5];
    const float* b3 = (const float*)d_in[6];
    float* out = (float*)d_out;

    dim3 grid12((H1 + BN - 1) / BN, B_ / BM);   // (8, 16)
    k_gemm1<<<grid12, 256>>>(x, w1, b1);
    k_gemm2<<<grid12, 256>>>(w2, b2);
    k_gemm3<<<B_, 256>>>(w3);
    k_scan<<<(B_ * NOUT + 255) / 256, 256>>>(b3, out);
}

// round 3
// speedup vs baseline: 1.5144x; 1.5144x over previous
#include <cuda_runtime.h>
#include <math.h>

// Problem dims (fixed by reference)
#define B_   1024
#define H1   500
#define IN_  784
#define NOUT 10
#define T_   100

#define BM 64
#define BN 64
#define BK 16

// Scratch (no device allocations allowed; referenced ONLY from device code)
__device__ float g_h[B_ * H1];
__device__ float g_drive[B_ * H1];
__device__ float g_u[B_ * NOUT];

// ---------------------------------------------------------------------------
// Double-buffered SGEMM body: C[M,N] = act(A[M,K] @ Bw[N,K]^T + bias[N])
// 64x64 tile, BK=16, 256 threads, 4x4 micro-tile, float4 LDG/LDS.
// ACT: 1 relu, 2 sigmoid. Accumulation order identical to R1 (k ascending).
// ---------------------------------------------------------------------------
template<int K, int N, int ACT>
__device__ __forceinline__ void gemm_body(const float* __restrict__ A,
                                          const float* __restrict__ Bw,
                                          const float* __restrict__ bias,
                                          float* __restrict__ C) {
    __shared__ float As[2][BK][BM];
    __shared__ float Bs[2][BK][BN];

    const int tid = threadIdx.x;           // 256 threads
    const int tx = tid & 15, ty = tid >> 4;
    const int m0 = blockIdx.y * BM, n0 = blockIdx.x * BN;
    const int lrow = tid >> 2;             // 0..63
    const int lcol = (tid & 3) * 4;        // 0,4,8,12
    const int KT = (K + BK - 1) / BK;

    const float* Arow = A + (size_t)(m0 + lrow) * K;
    const int gn = n0 + lrow;
    const float* Brow = Bw + (size_t)gn * K;
    const bool bvalid = (gn < N);

    float4 av, bv;
    // prologue: load tile 0 (lcol < 16 <= K always valid for A)
    av = *(const float4*)(Arow + lcol);
    bv = bvalid ? *(const float4*)(Brow + lcol) : make_float4(0.f, 0.f, 0.f, 0.f);
    As[0][lcol + 0][lrow] = av.x; As[0][lcol + 1][lrow] = av.y;
    As[0][lcol + 2][lrow] = av.z; As[0][lcol + 3][lrow] = av.w;
    Bs[0][lcol + 0][lrow] = bv.x; Bs[0][lcol + 1][lrow] = bv.y;
    Bs[0][lcol + 2][lrow] = bv.z; Bs[0][lcol + 3][lrow] = bv.w;
    __syncthreads();

    float acc[4][4];
#pragma unroll
    for (int i = 0; i < 4; i++)
#pragma unroll
        for (int j = 0; j < 4; j++) acc[i][j] = 0.0f;

    for (int kt = 0; kt < KT; kt++) {
        const int cur = kt & 1;
        const bool more = (kt + 1 < KT);
        if (more) {
            const int gk = (kt + 1) * BK + lcol;
            av = (gk < K) ? *(const float4*)(Arow + gk)
                          : make_float4(0.f, 0.f, 0.f, 0.f);
            bv = (bvalid && gk < K) ? *(const float4*)(Brow + gk)
                                    : make_float4(0.f, 0.f, 0.f, 0.f);
        }
#pragma unroll
        for (int kk = 0; kk < BK; kk++) {
            const float4 a = *(const float4*)&As[cur][kk][ty * 4];
            const float4 b = *(const float4*)&Bs[cur][kk][tx * 4];
            const float ar[4] = {a.x, a.y, a.z, a.w};
            const float br[4] = {b.x, b.y, b.z, b.w};
#pragma unroll
            for (int i = 0; i < 4; i++)
#pragma unroll
                for (int j = 0; j < 4; j++)
                    acc[i][j] = fmaf(ar[i], br[j], acc[i][j]);
        }
        if (more) {
            const int nx = (kt + 1) & 1;
            As[nx][lcol + 0][lrow] = av.x; As[nx][lcol + 1][lrow] = av.y;
            As[nx][lcol + 2][lrow] = av.z; As[nx][lcol + 3][lrow] = av.w;
            Bs[nx][lcol + 0][lrow] = bv.x; Bs[nx][lcol + 1][lrow] = bv.y;
            Bs[nx][lcol + 2][lrow] = bv.z; Bs[nx][lcol + 3][lrow] = bv.w;
            __syncthreads();
        }
    }

#pragma unroll
    for (int i = 0; i < 4; i++) {
        const int m = m0 + ty * 4 + i;
#pragma unroll
        for (int j = 0; j < 4; j++) {
            const int n = n0 + tx * 4 + j;
            if (n < N) {
                float x = acc[i][j] + bias[n];
                if (ACT == 1) x = fmaxf(x, 0.0f);
                if (ACT == 2) {
                    if (x >= 0.0f) {
                        x = 1.0f / (1.0f + expf(-x));
                    } else {
                        const float e = expf(x);
                        x = e / (1.0f + e);
                    }
                }
                C[(size_t)m * N + n] = x;
            }
        }
    }
}

// Wrappers: scratch globals referenced from DEVICE code (valid addresses).
__global__ void k_gemm1(const float* __restrict__ x,
                        const float* __restrict__ w1,
                        const float* __restrict__ b1) {
    gemm_body<IN_, H1, 1>(x, w1, b1, g_h);
}
__global__ void k_gemm2(const float* __restrict__ w2,
                        const float* __restrict__ b2) {
    gemm_body<H1, H1, 2>(g_h, w2, b2, g_drive);
}

// ---------------------------------------------------------------------------
// u[m,n] = sum_k drive[m,k] * w3[n,k]   (b3 added in the scan)
// (R1 version, proven rel_err 0.0 — summation order preserved.)
// ---------------------------------------------------------------------------
__global__ void k_gemm3(const float* __restrict__ w3) {
    const int m = blockIdx.x;
    __shared__ float row[H1];
    __shared__ float part[250];
    const int tid = threadIdx.x;  // 256
    for (int k = tid; k < H1; k += 256) row[k] = g_drive[m * H1 + k];
    __syncthreads();
    if (tid < 250) {
        const int n = tid / 25;
        const int ks = (tid % 25) * 20;
        float s = 0.0f;
#pragma unroll
        for (int k = 0; k < 20; k++)
            s = fmaf(row[ks + k], w3[n * H1 + ks + k], s);
        part[tid] = s;
    }
    __syncthreads();
    if (tid < NOUT) {
        float s = 0.0f;
#pragma unroll
        for (int p = 0; p < 25; p++) s += part[tid * 25 + p];
        g_u[m * NOUT + tid] = s;
    }
}

// ---------------------------------------------------------------------------
// LIF scan. c[t] (scalar, thread-independent) via fp64 closed form of the
// dual-exp IIR step response; per-thread chain is pure fp32.
// Exactness: sigma*v*(1-s) == (s?0:sigma)*v bit-for-bit (x*1.0, x*0 exact).
// Spikes staged in smem for coalesced stores.
// ---------------------------------------------------------------------------
__global__ void k_scan(const float* __restrict__ b3, float* __restrict__ out) {
    __shared__ float cf[T_];
    __shared__ float sbuf[256][25];        // stride 25 (odd) -> conflict-free

    const int tid = threadIdx.x;           // 256
    if (tid < T_) {
        const double r = 0.77880078307140487;   // exp(-1/4)
        const double q = 0.36787944117144233;   // exp(-1)
        const double tp1 = (double)(tid + 1);
        const double rp = exp(-0.25 * tp1);     // r^(t+1)
        const double qp = exp(-tp1);            // q^(t+1)
        const double c = (r * (1.0 - rp) / (1.0 - r)
                        - q * (1.0 - qp) / (1.0 - q)) / (r - q);
        cf[tid] = (float)c;
    }
    __syncthreads();

    const int id = blockIdx.x * 256 + tid; // 40 blocks -> 10240 exactly
    const int j = id % NOUT;
    const float uu = g_u[id];
    const float bb = b3[j];
    const float SIG = 0.77880078307140487f;

    float v = 0.0f;
    float f = SIG;                          // (s ? 0 : sigma); s0 = 0
    const int base = blockIdx.x * 256;

    for (int t0 = 0; t0 < T_; t0 += 25) {
#pragma unroll
        for (int tt = 0; tt < 25; tt++) {
            const float cur = __fadd_rn(__fmul_rn(cf[t0 + tt], uu), bb);
            v = __fadd_rn(__fmul_rn(f, v), cur);
            const float s = (v >= 1.0f) ? 1.0f : 0.0f;
            f = (v >= 1.0f) ? 0.0f : SIG;
            sbuf[tid][tt] = s;
        }
        __syncthreads();
#pragma unroll 5
        for (int q2 = 0; q2 < 25; q2++) {
            const int e = tid + 256 * q2;
            const int row = e / 25;
            const int col = e - row * 25;
            out[(size_t)(base + row) * T_ + t0 + col] = sbuf[row][col];
        }
        __syncthreads();
    }
}

extern "C" void kernel_launch(void* const* d_in, const int* in_sizes, int n_in,
                              void* d_out, int out_size) {
    const float* x  = (const float*)d_in[0];
    const float* w1 = (const float*)d_in[1];
    const float* b1 = (const float*)d_in[2];
    const float* w2 = (const float*)d_in[3];
    const float* b2 = (const float*)d_in[4];
    const float* w3 = (const float*)d_in[5];
    const float* b3 = (const float*)d_in[6];
    float* out = (float*)d_out;

    dim3 grid12((H1 + BN - 1) / BN, B_ / BM);   // (8, 16) = 128 blocks
    k_gemm1<<<grid12, 256>>>(x, w1, b1);
    k_gemm2<<<grid12, 256>>>(w2, b2);
    k_gemm3<<<B_, 256>>>(w3);
    k_scan<<<(B_ * NOUT) / 256, 256>>>(b3, out);
}

// round 4
// speedup vs baseline: 1.7155x; 1.1328x over previous
#include <cuda_runtime.h>
#include <math.h>

// Problem dims (fixed by reference)
#define B_   1024
#define H1   500
#define IN_  784
#define NOUT 10
#define T_   100

#define BM 64
#define BN 64
#define BK 32

// Scratch (no device allocations; referenced ONLY from device code)
__device__ float g_h[B_ * H1];
__device__ float g_drive[B_ * H1];
__device__ float g_u[B_ * NOUT];

// ---------------------------------------------------------------------------
// Double-buffered SGEMM body: C[M,N] = act(A[M,K] @ Bw[N,K]^T + bias[N])
// 64x64 tile, BK=32, 256 threads, 4x4 micro-tile, float4 LDG/LDS.
// ACT: 1 relu, 2 sigmoid. Accumulation strictly k-ascending (order-preserving
// vs R3 -> bit-identical results).
// ---------------------------------------------------------------------------
template<int K, int N, int ACT>
__device__ __forceinline__ void gemm_body(const float* __restrict__ A,
                                          const float* __restrict__ Bw,
                                          const float* __restrict__ bias,
                                          float* __restrict__ C) {
    __shared__ float As[2][BK][BM];
    __shared__ float Bs[2][BK][BN];

    const int tid = threadIdx.x;           // 256 threads
    const int tx = tid & 15, ty = tid >> 4;
    const int m0 = blockIdx.y * BM, n0 = blockIdx.x * BN;
    const int lrow = tid >> 2;             // 0..63
    const int lcol = (tid & 3) * 4;        // 0,4,8,12  (plus +16 second half)
    const int KT = (K + BK - 1) / BK;

    const float* Arow = A + (size_t)(m0 + lrow) * K;
    const int gn = n0 + lrow;
    const float* Brow = Bw + (size_t)gn * K;
    const bool bvalid = (gn < N);

    float4 av0, av1, bv0, bv1;
    // prologue: tile 0. K%4==0 so (gk<K) guards whole float4.
    {
        const int g0 = lcol, g1 = lcol + 16;
        av0 = (g0 < K) ? *(const float4*)(Arow + g0) : make_float4(0,0,0,0);
        av1 = (g1 < K) ? *(const float4*)(Arow + g1) : make_float4(0,0,0,0);
        bv0 = (bvalid && g0 < K) ? *(const float4*)(Brow + g0) : make_float4(0,0,0,0);
        bv1 = (bvalid && g1 < K) ? *(const float4*)(Brow + g1) : make_float4(0,0,0,0);
        As[0][lcol + 0][lrow] = av0.x; As[0][lcol + 1][lrow] = av0.y;
        As[0][lcol + 2][lrow] = av0.z; As[0][lcol + 3][lrow] = av0.w;
        As[0][lcol + 16][lrow] = av1.x; As[0][lcol + 17][lrow] = av1.y;
        As[0][lcol + 18][lrow] = av1.z; As[0][lcol + 19][lrow] = av1.w;
        Bs[0][lcol + 0][lrow] = bv0.x; Bs[0][lcol + 1][lrow] = bv0.y;
        Bs[0][lcol + 2][lrow] = bv0.z; Bs[0][lcol + 3][lrow] = bv0.w;
        Bs[0][lcol + 16][lrow] = bv1.x; Bs[0][lcol + 17][lrow] = bv1.y;
        Bs[0][lcol + 18][lrow] = bv1.z; Bs[0][lcol + 19][lrow] = bv1.w;
    }
    __syncthreads();

    float acc[4][4];
#pragma unroll
    for (int i = 0; i < 4; i++)
#pragma unroll
        for (int j = 0; j < 4; j++) acc[i][j] = 0.0f;

    for (int kt = 0; kt < KT; kt++) {
        const int cur = kt & 1;
        const bool more = (kt + 1 < KT);
        if (more) {
            const int g0 = (kt + 1) * BK + lcol;
            const int g1 = g0 + 16;
            av0 = (g0 < K) ? *(const float4*)(Arow + g0) : make_float4(0,0,0,0);
            av1 = (g1 < K) ? *(const float4*)(Arow + g1) : make_float4(0,0,0,0);
            bv0 = (bvalid && g0 < K) ? *(const float4*)(Brow + g0) : make_float4(0,0,0,0);
            bv1 = (bvalid && g1 < K) ? *(const float4*)(Brow + g1) : make_float4(0,0,0,0);
        }
#pragma unroll
        for (int kk = 0; kk < BK; kk++) {
            const float4 a = *(const float4*)&As[cur][kk][ty * 4];
            const float4 b = *(const float4*)&Bs[cur][kk][tx * 4];
            const float ar[4] = {a.x, a.y, a.z, a.w};
            const float br[4] = {b.x, b.y, b.z, b.w};
#pragma unroll
            for (int i = 0; i < 4; i++)
#pragma unroll
                for (int j = 0; j < 4; j++)
                    acc[i][j] = fmaf(ar[i], br[j], acc[i][j]);
        }
        if (more) {
            const int nx = (kt + 1) & 1;
            As[nx][lcol + 0][lrow] = av0.x; As[nx][lcol + 1][lrow] = av0.y;
            As[nx][lcol + 2][lrow] = av0.z; As[nx][lcol + 3][lrow] = av0.w;
            As[nx][lcol + 16][lrow] = av1.x; As[nx][lcol + 17][lrow] = av1.y;
            As[nx][lcol + 18][lrow] = av1.z; As[nx][lcol + 19][lrow] = av1.w;
            Bs[nx][lcol + 0][lrow] = bv0.x; Bs[nx][lcol + 1][lrow] = bv0.y;
            Bs[nx][lcol + 2][lrow] = bv0.z; Bs[nx][lcol + 3][lrow] = bv0.w;
            Bs[nx][lcol + 16][lrow] = bv1.x; Bs[nx][lcol + 17][lrow] = bv1.y;
            Bs[nx][lcol + 18][lrow] = bv1.z; Bs[nx][lcol + 19][lrow] = bv1.w;
            __syncthreads();
        }
    }

#pragma unroll
    for (int i = 0; i < 4; i++) {
        const int m = m0 + ty * 4 + i;
#pragma unroll
        for (int j = 0; j < 4; j++) {
            const int n = n0 + tx * 4 + j;
            if (n < N) {
                float x = acc[i][j] + bias[n];
                if (ACT == 1) x = fmaxf(x, 0.0f);
                if (ACT == 2) {
                    if (x >= 0.0f) {
                        x = 1.0f / (1.0f + expf(-x));
                    } else {
                        const float e = expf(x);
                        x = e / (1.0f + e);
                    }
                }
                C[(size_t)m * N + n] = x;
            }
        }
    }
}

__global__ void __launch_bounds__(256, 1)
k_gemm1(const float* __restrict__ x,
        const float* __restrict__ w1,
        const float* __restrict__ b1) {
    gemm_body<IN_, H1, 1>(x, w1, b1, g_h);
}
__global__ void __launch_bounds__(256, 1)
k_gemm2(const float* __restrict__ w2,
        const float* __restrict__ b2) {
    gemm_body<H1, H1, 2>(g_h, w2, b2, g_drive);
}

// ---------------------------------------------------------------------------
// u[m,n] = sum_k drive[m,k] * w3[n,k]   (b3 added in the scan)
// (R1 version, proven rel_err 0.0 — summation order preserved.)
// ---------------------------------------------------------------------------
__global__ void k_gemm3(const float* __restrict__ w3) {
    const int m = blockIdx.x;
    __shared__ float row[H1];
    __shared__ float part[250];
    const int tid = threadIdx.x;  // 256
    for (int k = tid; k < H1; k += 256) row[k] = g_drive[m * H1 + k];
    __syncthreads();
    if (tid < 250) {
        const int n = tid / 25;
        const int ks = (tid % 25) * 20;
        float s = 0.0f;
#pragma unroll
        for (int k = 0; k < 20; k++)
            s = fmaf(row[ks + k], w3[n * H1 + ks + k], s);
        part[tid] = s;
    }
    __syncthreads();
    if (tid < NOUT) {
        float s = 0.0f;
#pragma unroll
        for (int p = 0; p < 25; p++) s += part[tid * 25 + p];
        g_u[m * NOUT + tid] = s;
    }
}

// ---------------------------------------------------------------------------
// LIF scan, 80 blocks x 128 threads (one id per thread).
// Serial chain uses a sign-bit select (bit-exact vs predicate form):
//   spike  <=> v >= 1  <=>  sign(fl(v-1)) == 0   (sign of fl() exact;
//   Sterbenz gives exact v-1 on [0.5,2] so the boundary is exact).
//   f = sigma & signmask ; v' = fadd(fmul(f,v), cur) — identical to
//   sigma*v*(1-s)+cur for s in {0,1} (x*1 and x*0 exact, -0+c==c).
// Spikes packed to bits in registers; ONE __syncthreads; coalesced expand.
// ---------------------------------------------------------------------------
__global__ void __launch_bounds__(128, 8)
k_scan(const float* __restrict__ b3, float* __restrict__ out) {
    __shared__ float cf[T_];
    __shared__ unsigned sbits[128][4];

    const int tid = threadIdx.x;           // 128
    if (tid < T_) {
        const double r = 0.77880078307140487;   // exp(-1/4)
        const double q = 0.36787944117144233;   // exp(-1)
        const double tp1 = (double)(tid + 1);
        const double rp = exp(-0.25 * tp1);     // r^(t+1)
        const double qp = exp(-tp1);            // q^(t+1)
        const double c = (r * (1.0 - rp) / (1.0 - r)
                        - q * (1.0 - qp) / (1.0 - q)) / (r - q);
        cf[tid] = (float)c;
    }
    __syncthreads();

    const int base = blockIdx.x * 128;
    const int id = base + tid;             // 80 blocks * 128 = 10240 exactly
    const int j = id % NOUT;
    const float uu = g_u[id];
    const float bb = b3[j];
    const int SIGB = __float_as_int(0.77880078307140487f);

    float v = 0.0f;
    float f = __int_as_float(SIGB);        // s0 = 0 -> f = sigma
    unsigned sb0 = 0, sb1 = 0, sb2 = 0, sb3s = 0;

#pragma unroll
    for (int t = 0; t < T_; t++) {
        const float cur = __fadd_rn(__fmul_rn(cf[t], uu), bb);
        v = __fadd_rn(__fmul_rn(f, v), cur);
        const int tb = __float_as_int(__fadd_rn(v, -1.0f));
        const int smask = tb >> 31;        // all-ones if v < 1 (no spike)
        f = __int_as_float(SIGB & smask);
        const unsigned bit = (unsigned)(~smask) & 1u;  // 1 if spike
        if (t < 32)       sb0 |= bit << t;
        else if (t < 64)  sb1 |= bit << (t - 32);
        else if (t < 96)  sb2 |= bit << (t - 64);
        else              sb3s |= bit << (t - 96);
    }
    sbits[tid][0] = sb0; sbits[tid][1] = sb1;
    sbits[tid][2] = sb2; sbits[tid][3] = sb3s;
    __syncthreads();

    // expand: 128*100 floats per block, fully coalesced stores
    float* oblk = out + (size_t)base * T_;
#pragma unroll 4
    for (int qq = 0; qq < T_; qq++) {
        const int i = tid + 128 * qq;      // 0 .. 12799
        const int row = i / T_;
        const int t = i - row * T_;
        const unsigned w = sbits[row][t >> 5];
        oblk[i] = (float)((w >> (t & 31)) & 1u);
    }
}

extern "C" void kernel_launch(void* const* d_in, const int* in_sizes, int n_in,
                              void* d_out, int out_size) {
    const float* x  = (const float*)d_in[0];
    const float* w1 = (const float*)d_in[1];
    const float* b1 = (const float*)d_in[2];
    const float* w2 = (const float*)d_in[3];
    const float* b2 = (const float*)d_in[4];
    const float* w3 = (const float*)d_in[5];
    const float* b3 = (const float*)d_in[6];
    float* out = (float*)d_out;

    dim3 grid12((H1 + BN - 1) / BN, B_ / BM);   // (8, 16) = 128 blocks
    k_gemm1<<<grid12, 256>>>(x, w1, b1);
    k_gemm2<<<grid12, 256>>>(w2, b2);
    k_gemm3<<<B_, 256>>>(w3);
    k_scan<<<(B_ * NOUT) / 128, 128>>>(b3, out);
}

// round 5
// speedup vs baseline: 1.7311x; 1.0091x over previous
#include <cuda_runtime.h>
#include <math.h>

// Problem dims (fixed by reference)
#define B_   1024
#define H1   500
#define IN_  784
#define NOUT 10
#define T_   100

#define BM 64
#define BN 64
#define BK 32

// Scratch (no device allocations; referenced ONLY from device code)
__device__ float g_h[B_ * H1];
__device__ float g_drive[B_ * H1];
__device__ float g_cf[T_];

// ---------------------------------------------------------------------------
// Double-buffered SGEMM body: C[M,N] = act(A[M,K] @ Bw[N,K]^T + bias[N])
// 64x64 tile, BK=32, 256 threads, 4x4 micro-tile, float4 LDG/LDS.
// ACT: 1 relu, 2 sigmoid. Accumulation strictly k-ascending (bit-identical
// to R4).
// ---------------------------------------------------------------------------
template<int K, int N, int ACT>
__device__ __forceinline__ void gemm_body(const float* __restrict__ A,
                                          const float* __restrict__ Bw,
                                          const float* __restrict__ bias,
                                          float* __restrict__ C) {
    __shared__ float As[2][BK][BM];
    __shared__ float Bs[2][BK][BN];

    const int tid = threadIdx.x;           // 256 threads
    const int tx = tid & 15, ty = tid >> 4;
    const int m0 = blockIdx.y * BM, n0 = blockIdx.x * BN;
    const int lrow = tid >> 2;             // 0..63
    const int lcol = (tid & 3) * 4;        // 0,4,8,12  (+16 second half)
    const int KT = (K + BK - 1) / BK;

    const float* Arow = A + (size_t)(m0 + lrow) * K;
    const int gn = n0 + lrow;
    const float* Brow = Bw + (size_t)gn * K;
    const bool bvalid = (gn < N);

    float4 av0, av1, bv0, bv1;
    {
        const int g0 = lcol, g1 = lcol + 16;
        av0 = (g0 < K) ? *(const float4*)(Arow + g0) : make_float4(0,0,0,0);
        av1 = (g1 < K) ? *(const float4*)(Arow + g1) : make_float4(0,0,0,0);
        bv0 = (bvalid && g0 < K) ? *(const float4*)(Brow + g0) : make_float4(0,0,0,0);
        bv1 = (bvalid && g1 < K) ? *(const float4*)(Brow + g1) : make_float4(0,0,0,0);
        As[0][lcol + 0][lrow] = av0.x; As[0][lcol + 1][lrow] = av0.y;
        As[0][lcol + 2][lrow] = av0.z; As[0][lcol + 3][lrow] = av0.w;
        As[0][lcol + 16][lrow] = av1.x; As[0][lcol + 17][lrow] = av1.y;
        As[0][lcol + 18][lrow] = av1.z; As[0][lcol + 19][lrow] = av1.w;
        Bs[0][lcol + 0][lrow] = bv0.x; Bs[0][lcol + 1][lrow] = bv0.y;
        Bs[0][lcol + 2][lrow] = bv0.z; Bs[0][lcol + 3][lrow] = bv0.w;
        Bs[0][lcol + 16][lrow] = bv1.x; Bs[0][lcol + 17][lrow] = bv1.y;
        Bs[0][lcol + 18][lrow] = bv1.z; Bs[0][lcol + 19][lrow] = bv1.w;
    }
    __syncthreads();

    float acc[4][4];
#pragma unroll
    for (int i = 0; i < 4; i++)
#pragma unroll
        for (int j = 0; j < 4; j++) acc[i][j] = 0.0f;

    for (int kt = 0; kt < KT; kt++) {
        const int cur = kt & 1;
        const bool more = (kt + 1 < KT);
        if (more) {
            const int g0 = (kt + 1) * BK + lcol;
            const int g1 = g0 + 16;
            av0 = (g0 < K) ? *(const float4*)(Arow + g0) : make_float4(0,0,0,0);
            av1 = (g1 < K) ? *(const float4*)(Arow + g1) : make_float4(0,0,0,0);
            bv0 = (bvalid && g0 < K) ? *(const float4*)(Brow + g0) : make_float4(0,0,0,0);
            bv1 = (bvalid && g1 < K) ? *(const float4*)(Brow + g1) : make_float4(0,0,0,0);
        }
#pragma unroll
        for (int kk = 0; kk < BK; kk++) {
            const float4 a = *(const float4*)&As[cur][kk][ty * 4];
            const float4 b = *(const float4*)&Bs[cur][kk][tx * 4];
            const float ar[4] = {a.x, a.y, a.z, a.w};
            const float br[4] = {b.x, b.y, b.z, b.w};
#pragma unroll
            for (int i = 0; i < 4; i++)
#pragma unroll
                for (int j = 0; j < 4; j++)
                    acc[i][j] = fmaf(ar[i], br[j], acc[i][j]);
        }
        if (more) {
            const int nx = (kt + 1) & 1;
            As[nx][lcol + 0][lrow] = av0.x; As[nx][lcol + 1][lrow] = av0.y;
            As[nx][lcol + 2][lrow] = av0.z; As[nx][lcol + 3][lrow] = av0.w;
            As[nx][lcol + 16][lrow] = av1.x; As[nx][lcol + 17][lrow] = av1.y;
            As[nx][lcol + 18][lrow] = av1.z; As[nx][lcol + 19][lrow] = av1.w;
            Bs[nx][lcol + 0][lrow] = bv0.x; Bs[nx][lcol + 1][lrow] = bv0.y;
            Bs[nx][lcol + 2][lrow] = bv0.z; Bs[nx][lcol + 3][lrow] = bv0.w;
            Bs[nx][lcol + 16][lrow] = bv1.x; Bs[nx][lcol + 17][lrow] = bv1.y;
            Bs[nx][lcol + 18][lrow] = bv1.z; Bs[nx][lcol + 19][lrow] = bv1.w;
            __syncthreads();
        }
    }

#pragma unroll
    for (int i = 0; i < 4; i++) {
        const int m = m0 + ty * 4 + i;
#pragma unroll
        for (int j = 0; j < 4; j++) {
            const int n = n0 + tx * 4 + j;
            if (n < N) {
                float x = acc[i][j] + bias[n];
                if (ACT == 1) x = fmaxf(x, 0.0f);
                if (ACT == 2) {
                    if (x >= 0.0f) {
                        x = 1.0f / (1.0f + expf(-x));
                    } else {
                        const float e = expf(x);
                        x = e / (1.0f + e);
                    }
                }
                C[(size_t)m * N + n] = x;
            }
        }
    }
}

// gemm1 + one extra block column that computes cf[] (fp64 closed form of the
// dual-exp IIR step response) into g_cf. Formula/ops identical to R4 ->
// bit-identical float coefficients.
__global__ void __launch_bounds__(256, 1)
k_gemm1(const float* __restrict__ x,
        const float* __restrict__ w1,
        const float* __restrict__ b1) {
    if (blockIdx.x == 8) {
        if (blockIdx.y == 0 && threadIdx.x < T_) {
            const double r = 0.77880078307140487;   // exp(-1/4)
            const double q = 0.36787944117144233;   // exp(-1)
            const double tp1 = (double)(threadIdx.x + 1);
            const double rp = exp(-0.25 * tp1);     // r^(t+1)
            const double qp = exp(-tp1);            // q^(t+1)
            const double c = (r * (1.0 - rp) / (1.0 - r)
                            - q * (1.0 - qp) / (1.0 - q)) / (r - q);
            g_cf[threadIdx.x] = (float)c;
        }
        return;
    }
    gemm_body<IN_, H1, 1>(x, w1, b1, g_h);
}

__global__ void __launch_bounds__(256, 1)
k_gemm2(const float* __restrict__ w2,
        const float* __restrict__ b2) {
    gemm_body<H1, H1, 2>(g_h, w2, b2, g_drive);
}

// ---------------------------------------------------------------------------
// Fused gemm3 + LIF scan. One block per batch row m.
//   u[n] = sum_k drive[m,k] * w3[n,k]   (identical reduction order to R4)
//   chain: v = fadd(fmul(f,v), fadd(fmul(cf[t],u), b3));
//          f = sigma & signmask(fl(v-1))   (bit-exact sign-bit select)
// Spikes bit-packed in smem; 256 threads expand 10x100 floats coalesced.
// ---------------------------------------------------------------------------
__global__ void __launch_bounds__(256, 8)
k_fused3(const float* __restrict__ w3,
         const float* __restrict__ b3,
         float* __restrict__ out) {
    const int m = blockIdx.x;
    __shared__ float row[H1];
    __shared__ float part[250];
    __shared__ float cf[T_];
    __shared__ unsigned sbits[NOUT][4];

    const int tid = threadIdx.x;  // 256
    for (int k = tid; k < H1; k += 256) row[k] = g_drive[m * H1 + k];
    if (tid < T_) cf[tid] = g_cf[tid];
    __syncthreads();

    if (tid < 250) {
        const int n = tid / 25;
        const int ks = (tid % 25) * 20;
        float s = 0.0f;
#pragma unroll
        for (int k = 0; k < 20; k++)
            s = fmaf(row[ks + k], w3[n * H1 + ks + k], s);
        part[tid] = s;
    }
    __syncthreads();

    if (tid < NOUT) {
        float u = 0.0f;
#pragma unroll
        for (int p = 0; p < 25; p++) u += part[tid * 25 + p];

        const float bb = b3[tid];
        const int SIGB = __float_as_int(0.77880078307140487f);
        float v = 0.0f;
        float f = __int_as_float(SIGB);     // s0 = 0 -> f = sigma
        unsigned sb0 = 0, sb1 = 0, sb2 = 0, sb3v = 0;
#pragma unroll
        for (int t = 0; t < T_; t++) {
            const float cur = __fadd_rn(__fmul_rn(cf[t], u), bb);
            v = __fadd_rn(__fmul_rn(f, v), cur);
            const int tb = __float_as_int(__fadd_rn(v, -1.0f));
            const int smask = tb >> 31;     // all-ones if v < 1 (no spike)
            f = __int_as_float(SIGB & smask);
            const unsigned bit = (unsigned)(~smask) & 1u;  // 1 if spike
            if (t < 32)       sb0 |= bit << t;
            else if (t < 64)  sb1 |= bit << (t - 32);
            else if (t < 96)  sb2 |= bit << (t - 64);
            else              sb3v |= bit << (t - 96);
        }
        sbits[tid][0] = sb0; sbits[tid][1] = sb1;
        sbits[tid][2] = sb2; sbits[tid][3] = sb3v;
    }
    __syncthreads();

    // expand: NOUT*T_ = 1000 floats per block, coalesced
    float* oblk = out + (size_t)m * NOUT * T_;
#pragma unroll
    for (int i = tid; i < NOUT * T_; i += 256) {
        const int n = i / T_;
        const int t = i - n * T_;
        const unsigned w = sbits[n][t >> 5];
        oblk[i] = (float)((w >> (t & 31)) & 1u);
    }
}

extern "C" void kernel_launch(void* const* d_in, const int* in_sizes, int n_in,
                              void* d_out, int out_size) {
    const float* x  = (const float*)d_in[0];
    const float* w1 = (const float*)d_in[1];
    const float* b1 = (const float*)d_in[2];
    const float* w2 = (const float*)d_in[3];
    const float* b2 = (const float*)d_in[4];
    const float* w3 = (const float*)d_in[5];
    const float* b3 = (const float*)d_in[6];
    float* out = (float*)d_out;

    dim3 grid1(9, B_ / BM);                 // 8 gemm cols + 1 cf column
    dim3 grid2((H1 + BN - 1) / BN, B_ / BM);
    k_gemm1<<<grid1, 256>>>(x, w1, b1);
    k_gemm2<<<grid2, 256>>>(w2, b2);
    k_fused3<<<B_, 256>>>(w3, b3, out);
}